// round 11
// baseline (speedup 1.0000x reference)
#include <cuda_runtime.h>
#include <cuda_fp16.h>
#include <cstdint>

// ============================================================
// Problem constants
// ============================================================
#define BB 2
#define SS 2048
#define DD 1536
#define HH 12
#define HD 128
#define KK 1536                 // GEMM K (plain fp16)
#define MM 4096                 // BB * SS
#define OUT1_ELEMS (MM * DD)    // 6291456
#define ATTN_ELEMS (BB * HH * SS * SS)  // 100663296
#define NROWS (BB * HH * SS)    // 49152 attn_weights rows
#define QCH 256                 // q-chunk for prefix scan
#define NCH (SS / QCH)          // 8 chunks

// GEMM tiling
#define BM 128
#define BN 128
#define BK 32
#define STG 4
#define ROWB 80                  // smem row stride in bytes -- conflict-free ldmatrix
#define TILEB (128 * ROWB)       // 10240 bytes per A or B tile
#define STAGEB (2 * TILEB)       // 20480 bytes per stage
#define GEMM_SMEM (STG * STAGEB) // 81920
#define NTILES ((DD / BN) * (MM / BM))   // 384 GEMM CTAs

// attn_weights writer CTAs (dedicated, low block indices, TMA bulk stores)
#define AWC 148

// ============================================================
// Scratch (__device__ globals -- no allocation allowed)
// ============================================================
__device__ __half g_Xs[(size_t)MM * KK];   // fp16(hidden)
__device__ __half g_As[(size_t)MM * KK];   // fp16(attn out)
__device__ __half g_Ws1[(size_t)DD * KK];  // fp16(W_fc)
__device__ __half g_Ws2[(size_t)DD * KK];  // fp16(W_proj)
__device__ float  g_V[(size_t)MM * DD];    // fc output (value states)
__device__ float  g_P[(size_t)BB * HH * SS * HD];       // per-chunk local prefix

// ============================================================
// PTX helpers (sm_80/sm_90-era instructions only; no tcgen05)
// ============================================================
__device__ __forceinline__ uint32_t smem_to_u32(const void* p) {
    uint32_t a;
    asm("{ .reg .u64 t; cvta.to.shared.u64 t, %1; cvt.u32.u64 %0, t; }"
        : "=r"(a) : "l"(p));
    return a;
}

#define CP16(smem_u32, gptr) \
    asm volatile("cp.async.cg.shared.global [%0], [%1], 16;" \
        :: "r"(smem_u32), "l"(gptr))

#define CP_COMMIT() asm volatile("cp.async.commit_group;" ::: "memory")
#define CP_WAIT(n)  asm volatile("cp.async.wait_group %0;" :: "n"(n) : "memory")

__device__ __forceinline__ void ldsm_x4(uint32_t& r0, uint32_t& r1,
                                        uint32_t& r2, uint32_t& r3,
                                        uint32_t addr) {
    asm volatile("ldmatrix.sync.aligned.m8n8.x4.shared.b16 {%0,%1,%2,%3}, [%4];"
                 : "=r"(r0), "=r"(r1), "=r"(r2), "=r"(r3) : "r"(addr));
}

__device__ __forceinline__ void mma16816(float* c, const uint32_t* a,
                                         const uint32_t* b) {
    asm volatile(
        "mma.sync.aligned.m16n8k16.row.col.f32.f16.f16.f32 "
        "{%0,%1,%2,%3}, {%4,%5,%6,%7}, {%8,%9}, {%0,%1,%2,%3};"
        : "+f"(c[0]), "+f"(c[1]), "+f"(c[2]), "+f"(c[3])
        : "r"(a[0]), "r"(a[1]), "r"(a[2]), "r"(a[3]), "r"(b[0]), "r"(b[1]));
}

// ============================================================
// Kernel 1: fp32 -> fp16 convert (4 elements / thread)
// ============================================================
__global__ void __launch_bounds__(256)
cvt_kernel(const float4* __restrict__ src, uint2* __restrict__ dst, int n4) {
    int i = blockIdx.x * 256 + threadIdx.x;
    if (i >= n4) return;
    float4 v = src[i];
    __half2 p0 = __halves2half2(__float2half_rn(v.x), __float2half_rn(v.y));
    __half2 p1 = __halves2half2(__float2half_rn(v.z), __float2half_rn(v.w));
    uint2 o;
    o.x = *reinterpret_cast<uint32_t*>(&p0);
    o.y = *reinterpret_cast<uint32_t*>(&p1);
    dst[i] = o;
}

// ============================================================
// Kernel 2: FUSED fp16 GEMM + TMA-bulk attn_weights writer.
// blockIdx.x <  AWC : writer CTA -- builds 8KB rows in double-buffered
//                     smem and drains them with cp.async.bulk (TMA path,
//                     bypassing the STG/L1tex pipeline the GEMM needs).
// blockIdx.x >= AWC : GEMM CTA (unchanged 128x128x32 pipeline).
// ============================================================
__global__ void __launch_bounds__(256, 2)
gemm_fp16_aw(const __half* __restrict__ A, const __half* __restrict__ Bw,
             float* __restrict__ C, const float* __restrict__ bias,
             float* __restrict__ aw, int awR0, int awR1) {
    // ---------------- writer role (TMA bulk stores) ----------------
    if (blockIdx.x < AWC) {
        if (aw == nullptr) return;
        extern __shared__ char smemw[];
        const uint32_t sb = smem_to_u32(smemw);
        float* buf = reinterpret_cast<float*>(smemw);  // 2 x 2048 floats
        const int tid = threadIdx.x;
        const int k0 = tid * 8;
        int i = 0;
        for (int row = awR0 + blockIdx.x; row < awR1; row += AWC, ++i) {
            const int slot = i & 1;
            // recycle slot: the bulk store issued 2 iterations ago must have
            // finished READING this buffer before we overwrite it
            if (i >= 2 && tid == 0)
                asm volatile("cp.async.bulk.wait_group.read 1;" ::: "memory");
            __syncthreads();

            const int q = row & (SS - 1);
            const int h = (row >> 11) % HH;
            const int w = (1 << (h + 1)) - 1;
            const int lo = q - w + 1;
            const int len = (q + 1 < w) ? (q + 1) : w;
            const float inv = 1.0f / (float)len;
            float* bp = buf + slot * 2048;
#pragma unroll
            for (int j = 0; j < 8; ++j) {
                const int k = k0 + j;
                bp[k] = (k <= q && k >= lo) ? inv : 0.0f;
            }
            // make smem writes visible to the async proxy, then issue
            asm volatile("fence.proxy.async.shared::cta;" ::: "memory");
            __syncthreads();
            if (tid == 0) {
                asm volatile(
                    "cp.async.bulk.global.shared::cta.bulk_group [%0], [%1], %2;"
                    :: "l"(aw + (size_t)row * SS),
                       "r"(sb + (uint32_t)slot * 8192u), "r"(8192u)
                    : "memory");
                asm volatile("cp.async.bulk.commit_group;" ::: "memory");
            }
        }
        if (tid == 0)
            asm volatile("cp.async.bulk.wait_group.read 0;" ::: "memory");
        return;
    }

    // ---------------- GEMM role ----------------
    const int bxy = blockIdx.x - AWC;
    const int bx = bxy % (DD / BN);   // N tile
    const int by = bxy / (DD / BN);   // M tile

    extern __shared__ char smem[];
    const uint32_t sb = smem_to_u32(smem);
    const int tid = threadIdx.x;
    const int lane = tid & 31;
    const int warp = tid >> 5;
    const int warpM = warp >> 2;   // 0..1 (64 rows each)
    const int warpN = warp & 3;    // 0..3 (32 cols each)

    const int ldRow = tid >> 1;
    const int ldCol = (tid & 1) * 2;
    const __half* gA = A + ((size_t)by * BM + ldRow) * KK + ldCol * 8;
    const __half* gB = Bw + ((size_t)bx * BN + ldRow) * KK + ldCol * 8;
    const uint32_t stOff = (uint32_t)ldRow * ROWB + (uint32_t)ldCol * 16;

    const int aRow = (lane & 7) + ((lane >> 3) & 1) * 8;
    const uint32_t aBase = sb + (uint32_t)(warpM * 64 + aRow) * ROWB
                              + (uint32_t)(lane >> 4) * 16;
    const int bRow = (lane & 7) + ((lane >> 4) & 1) * 8;
    const uint32_t bBase = sb + TILEB + (uint32_t)(warpN * 32 + bRow) * ROWB
                              + (uint32_t)((lane >> 3) & 1) * 16;

    float acc[4][4][4];
#pragma unroll
    for (int i = 0; i < 4; ++i)
#pragma unroll
        for (int j = 0; j < 4; ++j)
#pragma unroll
            for (int k = 0; k < 4; ++k) acc[i][j][k] = 0.0f;

    const int NIT = KK / BK;  // 48

#pragma unroll
    for (int s = 0; s < STG - 1; ++s) {
        const uint32_t base = sb + s * STAGEB;
        const __half* ga = gA + s * BK;
        const __half* gb = gB + s * BK;
        CP16(base + stOff, ga);
        CP16(base + stOff + 16, ga + 8);
        CP16(base + TILEB + stOff, gb);
        CP16(base + TILEB + stOff + 16, gb + 8);
        CP_COMMIT();
    }

    for (int it = 0; it < NIT; ++it) {
        CP_WAIT(STG - 2);
        __syncthreads();

        const int pf = it + STG - 1;
        if (pf < NIT) {
            const uint32_t base = sb + (pf & (STG - 1)) * STAGEB;
            const __half* ga = gA + pf * BK;
            const __half* gb = gB + pf * BK;
            CP16(base + stOff, ga);
            CP16(base + stOff + 16, ga + 8);
            CP16(base + TILEB + stOff, gb);
            CP16(base + TILEB + stOff + 16, gb + 8);
        }
        CP_COMMIT();

        const uint32_t soff = (it & (STG - 1)) * STAGEB;
#pragma unroll
        for (int kk = 0; kk < 2; ++kk) {
            uint32_t a[4][4];
            uint32_t b[4][2];
#pragma unroll
            for (int mt = 0; mt < 4; ++mt)
                ldsm_x4(a[mt][0], a[mt][1], a[mt][2], a[mt][3],
                        aBase + soff + (uint32_t)mt * (16 * ROWB) + kk * 32);
            ldsm_x4(b[0][0], b[0][1], b[1][0], b[1][1],
                    bBase + soff + kk * 32);
            ldsm_x4(b[2][0], b[2][1], b[3][0], b[3][1],
                    bBase + soff + (16 * ROWB) + kk * 32);
#pragma unroll
            for (int mt = 0; mt < 4; ++mt)
#pragma unroll
                for (int nt = 0; nt < 4; ++nt)
                    mma16816(acc[mt][nt], a[mt], b[nt]);
        }
    }

    const int r0 = by * BM + warpM * 64 + (lane >> 2);
    const int c0 = bx * BN + warpN * 32 + (lane & 3) * 2;
#pragma unroll
    for (int nt = 0; nt < 4; ++nt) {
        const int col = c0 + nt * 8;
        const float bx2 = bias[col], by2 = bias[col + 1];
#pragma unroll
        for (int mt = 0; mt < 4; ++mt) {
            const int row = r0 + mt * 16;
            float2 v0 = make_float2(acc[mt][nt][0] + bx2, acc[mt][nt][1] + by2);
            float2 v1 = make_float2(acc[mt][nt][2] + bx2, acc[mt][nt][3] + by2);
            *reinterpret_cast<float2*>(C + (size_t)row * DD + col) = v0;
            *reinterpret_cast<float2*>(C + (size_t)(row + 8) * DD + col) = v1;
        }
    }
}

// ============================================================
// Kernel 3: FUSED window-mean attention (scan + output in one kernel).
// Grid: B*H*2 = 48 CTAs, 512 threads = (chunk c in 0..7) x (d-half 0..63).
// ============================================================
__global__ void __launch_bounds__(512)
attn_fused_kernel() {
    __shared__ float tot[NCH][64 + 1];

    const int half = blockIdx.x & 1;
    const int bh = blockIdx.x >> 1;
    const int b = bh / HH;
    const int h = bh % HH;
    const int c = threadIdx.x >> 6;          // 0..7
    const int dl = threadIdx.x & 63;
    const int d = half * 64 + dl;
    const int w = (1 << (h + 1)) - 1;
    const int q0 = c * QCH;

    const float* vp = g_V + ((size_t)b * SS + q0) * DD + h * HD + d;
    float* pp = g_P + ((size_t)(b * HH + h) * SS + q0) * HD + d;
    float acc = 0.0f;
#pragma unroll 8
    for (int i = 0; i < QCH; ++i) {
        acc += vp[(size_t)i * DD];
        pp[(size_t)i * HD] = acc;
    }
    tot[c][dl] = acc;
    __syncthreads();

    const int c2a = (q0 - w) >> 8;           // arithmetic shift; may be negative
    float run = 0.0f, offc = 0.0f, offA = 0.0f, offB = 0.0f;
#pragma unroll
    for (int cc = 0; cc < NCH; ++cc) {
        if (cc == c)       offc = run;
        if (cc == c2a)     offA = run;
        if (cc == c2a + 1) offB = run;
        run += tot[cc][dl];
    }

    const float* Pb = g_P + (size_t)(b * HH + h) * SS * HD + d;
    __half* op = g_As + ((size_t)b * SS + q0) * KK + (size_t)h * HD + d;
    const float invw = 1.0f / (float)w;
#pragma unroll 4
    for (int i = 0; i < QCH; ++i) {
        const int q = q0 + i;
        const float Pq = Pb[(size_t)q * HD] + offc;
        const int q2 = q - w;
        float prev, inv;
        if (q2 >= 0) {
            const int cc2 = q2 >> 8;
            const float off2 = (cc2 == c2a) ? offA : offB;
            prev = Pb[(size_t)q2 * HD] + off2;
            inv = invw;
        } else {
            prev = 0.0f;
            inv = 1.0f / (float)(q + 1);
        }
        op[(size_t)i * KK] = __float2half_rn((Pq - prev) * inv);
    }
}

// ============================================================
// Host launcher -- single stream; overlap inside fused kernels
// ============================================================
extern "C" void kernel_launch(void* const* d_in, const int* in_sizes, int n_in,
                              void* d_out, int out_size) {
    const float* hs  = (const float*)d_in[0];
    const float* Wfc = (const float*)d_in[1];
    const float* bfc = (const float*)d_in[2];
    const float* Wpj = (const float*)d_in[3];
    const float* bpj = (const float*)d_in[4];
    float* out = (float*)d_out;

    void *pXs, *pAs, *pWs1, *pWs2, *pV;
    cudaGetSymbolAddress(&pXs,  g_Xs);
    cudaGetSymbolAddress(&pAs,  g_As);
    cudaGetSymbolAddress(&pWs1, g_Ws1);
    cudaGetSymbolAddress(&pWs2, g_Ws2);
    cudaGetSymbolAddress(&pV,   g_V);

    cudaFuncSetAttribute(gemm_fp16_aw,
                         cudaFuncAttributeMaxDynamicSharedMemorySize, GEMM_SMEM);

    long long need = (long long)OUT1_ELEMS + (long long)ATTN_ELEMS;
    float* aw = ((long long)out_size >= need) ? (out + OUT1_ELEMS) : nullptr;

    // 1) fp32 -> fp16 converts
    cvt_kernel<<<(OUT1_ELEMS / 4 + 255) / 256, 256>>>(
        (const float4*)hs, (uint2*)pXs, OUT1_ELEMS / 4);
    cvt_kernel<<<(DD * DD / 4 + 255) / 256, 256>>>(
        (const float4*)Wfc, (uint2*)pWs1, DD * DD / 4);
    cvt_kernel<<<(DD * DD / 4 + 255) / 256, 256>>>(
        (const float4*)Wpj, (uint2*)pWs2, DD * DD / 4);

    // 2) V = X @ W_fc^T + b_fc   (+ first half of attn_weights via TMA)
    gemm_fp16_aw<<<AWC + NTILES, 256, GEMM_SMEM>>>(
        (const __half*)pXs, (const __half*)pWs1, (float*)pV, bfc,
        aw, 0, NROWS / 2);

    // 3) fused window-mean attention -> g_As (fp16)
    attn_fused_kernel<<<BB * HH * 2, 512>>>();

    // 4) out = attn_out @ W_proj^T + b_proj  (+ second half via TMA)
    gemm_fp16_aw<<<AWC + NTILES, 256, GEMM_SMEM>>>(
        (const __half*)pAs, (const __half*)pWs2, out, bpj,
        aw, NROWS / 2, NROWS);
}

// round 12
// speedup vs baseline: 1.1606x; 1.1606x over previous
#include <cuda_runtime.h>
#include <cuda_fp16.h>
#include <cstdint>

// ============================================================
// Problem constants
// ============================================================
#define BB 2
#define SS 2048
#define DD 1536
#define HH 12
#define HD 128
#define KK 1536                 // GEMM K (plain fp16)
#define MM 4096                 // BB * SS
#define OUT1_ELEMS (MM * DD)    // 6291456
#define ATTN_ELEMS (BB * HH * SS * SS)  // 100663296
#define NROWS (BB * HH * SS)    // 49152 attn_weights rows
#define QCH 256                 // q-chunk for prefix scan
#define NCH (SS / QCH)          // 8 chunks

// GEMM tiling
#define BM 128
#define BN 128
#define BK 32
#define STG 4
#define ROWB 80                  // smem row stride in bytes -- conflict-free ldmatrix
#define TILEB (128 * ROWB)       // 10240 bytes per A or B tile
#define STAGEB (2 * TILEB)       // 20480 bytes per stage
#define GEMM_SMEM (STG * STAGEB) // 81920
#define NTILES ((DD / BN) * (MM / BM))   // 384 GEMM CTAs

// writer CTAs fused into every launch (low block indices)
#define AWC 148

// attn_weights row distribution across the 4 launches
#define CVT_ROWS  1024
#define ATTN_ROWS 1536
#define G1_ROW0   (CVT_ROWS + ATTN_ROWS)            // 2560
#define G1_ROW1   (G1_ROW0 + (NROWS - G1_ROW0) / 2) // 25856
// gemm2 covers [G1_ROW1, NROWS)

// cvt sizes (in float4 units)
#define N4_X  (OUT1_ELEMS / 4)        // 1572864
#define N4_W  (DD * DD / 4)           // 589824
#define N4_ALL (N4_X + 2 * N4_W)      // 2752512
#define CVT_CTAS ((N4_ALL + 255) / 256)

// ============================================================
// Scratch (__device__ globals -- no allocation allowed)
// ============================================================
__device__ __half g_Xs[(size_t)MM * KK];   // fp16(hidden)
__device__ __half g_As[(size_t)MM * KK];   // fp16(attn out)
__device__ __half g_Ws1[(size_t)DD * KK];  // fp16(W_fc)
__device__ __half g_Ws2[(size_t)DD * KK];  // fp16(W_proj)
__device__ float  g_V[(size_t)MM * DD];    // fc output (value states)
__device__ float  g_P[(size_t)BB * HH * SS * HD];       // per-chunk local prefix

// ============================================================
// PTX helpers
// ============================================================
__device__ __forceinline__ uint32_t smem_to_u32(const void* p) {
    uint32_t a;
    asm("{ .reg .u64 t; cvta.to.shared.u64 t, %1; cvt.u32.u64 %0, t; }"
        : "=r"(a) : "l"(p));
    return a;
}

#define CP16(smem_u32, gptr) \
    asm volatile("cp.async.cg.shared.global [%0], [%1], 16;" \
        :: "r"(smem_u32), "l"(gptr))

#define CP_COMMIT() asm volatile("cp.async.commit_group;" ::: "memory")
#define CP_WAIT(n)  asm volatile("cp.async.wait_group %0;" :: "n"(n) : "memory")

__device__ __forceinline__ void ldsm_x4(uint32_t& r0, uint32_t& r1,
                                        uint32_t& r2, uint32_t& r3,
                                        uint32_t addr) {
    asm volatile("ldmatrix.sync.aligned.m8n8.x4.shared.b16 {%0,%1,%2,%3}, [%4];"
                 : "=r"(r0), "=r"(r1), "=r"(r2), "=r"(r3) : "r"(addr));
}

__device__ __forceinline__ void mma16816(float* c, const uint32_t* a,
                                         const uint32_t* b) {
    asm volatile(
        "mma.sync.aligned.m16n8k16.row.col.f32.f16.f16.f32 "
        "{%0,%1,%2,%3}, {%4,%5,%6,%7}, {%8,%9}, {%0,%1,%2,%3};"
        : "+f"(c[0]), "+f"(c[1]), "+f"(c[2]), "+f"(c[3])
        : "r"(a[0]), "r"(a[1]), "r"(a[2]), "r"(a[3]), "r"(b[0]), "r"(b[1]));
}

// ------------------------------------------------------------
// Generic attn_weights row writer: nthreads threads cover 2048 floats.
// fpt = floats per thread (2048/nthreads), must be a multiple of 4.
// ------------------------------------------------------------
template <int NT>
__device__ __forceinline__ void aw_rows(float* __restrict__ aw,
                                        int r0, int r1, int tid) {
    const int fpt = 2048 / NT;  // 8 for NT=256, 4 for NT=512
    const int k0 = tid * fpt;
    for (int row = r0 + blockIdx.x; row < r1; row += AWC) {
        const int q = row & (SS - 1);
        const int h = (row >> 11) % HH;
        const int w = (1 << (h + 1)) - 1;
        const int lo = q - w + 1;
        const int len = (q + 1 < w) ? (q + 1) : w;
        const float inv = 1.0f / (float)len;
        float* p = aw + (size_t)row * SS + k0;
#pragma unroll
        for (int j = 0; j < fpt; j += 4) {
            float4 v;
            int k;
            k = k0 + j + 0; v.x = (k <= q && k >= lo) ? inv : 0.0f;
            k = k0 + j + 1; v.y = (k <= q && k >= lo) ? inv : 0.0f;
            k = k0 + j + 2; v.z = (k <= q && k >= lo) ? inv : 0.0f;
            k = k0 + j + 3; v.w = (k <= q && k >= lo) ? inv : 0.0f;
            __stcs(reinterpret_cast<float4*>(p + j), v);
        }
    }
}

// ============================================================
// Kernel 1: merged fp32->fp16 convert (X, W_fc, W_proj) + writer CTAs
// ============================================================
__global__ void __launch_bounds__(256)
cvt_all_aw(const float4* __restrict__ hs, const float4* __restrict__ wfc,
           const float4* __restrict__ wpj, uint2* __restrict__ xs,
           uint2* __restrict__ w1, uint2* __restrict__ w2,
           float* __restrict__ aw) {
    if (blockIdx.x < AWC) {
        if (aw != nullptr) aw_rows<256>(aw, 0, CVT_ROWS, threadIdx.x);
        return;
    }
    int i = (blockIdx.x - AWC) * 256 + threadIdx.x;
    if (i >= N4_ALL) return;
    const float4* src;
    uint2* dst;
    int j;
    if (i < N4_X)            { src = hs;  dst = xs; j = i; }
    else if (i < N4_X + N4_W){ src = wfc; dst = w1; j = i - N4_X; }
    else                     { src = wpj; dst = w2; j = i - N4_X - N4_W; }
    float4 v = src[j];
    __half2 p0 = __halves2half2(__float2half_rn(v.x), __float2half_rn(v.y));
    __half2 p1 = __halves2half2(__float2half_rn(v.z), __float2half_rn(v.w));
    uint2 o;
    o.x = *reinterpret_cast<uint32_t*>(&p0);
    o.y = *reinterpret_cast<uint32_t*>(&p1);
    dst[j] = o;
}

// ============================================================
// Kernel 2: FUSED fp16 GEMM + attn_weights row writer (R9 structure).
// ============================================================
__global__ void __launch_bounds__(256, 2)
gemm_fp16_aw(const __half* __restrict__ A, const __half* __restrict__ Bw,
             float* __restrict__ C, const float* __restrict__ bias,
             float* __restrict__ aw, int awR0, int awR1) {
    if (blockIdx.x < AWC) {
        if (aw != nullptr) aw_rows<256>(aw, awR0, awR1, threadIdx.x);
        return;
    }

    const int bxy = blockIdx.x - AWC;
    const int bx = bxy % (DD / BN);   // N tile
    const int by = bxy / (DD / BN);   // M tile

    extern __shared__ char smem[];
    const uint32_t sb = smem_to_u32(smem);
    const int tid = threadIdx.x;
    const int lane = tid & 31;
    const int warp = tid >> 5;
    const int warpM = warp >> 2;
    const int warpN = warp & 3;

    const int ldRow = tid >> 1;
    const int ldCol = (tid & 1) * 2;
    const __half* gA = A + ((size_t)by * BM + ldRow) * KK + ldCol * 8;
    const __half* gB = Bw + ((size_t)bx * BN + ldRow) * KK + ldCol * 8;
    const uint32_t stOff = (uint32_t)ldRow * ROWB + (uint32_t)ldCol * 16;

    const int aRow = (lane & 7) + ((lane >> 3) & 1) * 8;
    const uint32_t aBase = sb + (uint32_t)(warpM * 64 + aRow) * ROWB
                              + (uint32_t)(lane >> 4) * 16;
    const int bRow = (lane & 7) + ((lane >> 4) & 1) * 8;
    const uint32_t bBase = sb + TILEB + (uint32_t)(warpN * 32 + bRow) * ROWB
                              + (uint32_t)((lane >> 3) & 1) * 16;

    float acc[4][4][4];
#pragma unroll
    for (int i = 0; i < 4; ++i)
#pragma unroll
        for (int j = 0; j < 4; ++j)
#pragma unroll
            for (int k = 0; k < 4; ++k) acc[i][j][k] = 0.0f;

    const int NIT = KK / BK;  // 48

#pragma unroll
    for (int s = 0; s < STG - 1; ++s) {
        const uint32_t base = sb + s * STAGEB;
        const __half* ga = gA + s * BK;
        const __half* gb = gB + s * BK;
        CP16(base + stOff, ga);
        CP16(base + stOff + 16, ga + 8);
        CP16(base + TILEB + stOff, gb);
        CP16(base + TILEB + stOff + 16, gb + 8);
        CP_COMMIT();
    }

    for (int it = 0; it < NIT; ++it) {
        CP_WAIT(STG - 2);
        __syncthreads();

        const int pf = it + STG - 1;
        if (pf < NIT) {
            const uint32_t base = sb + (pf & (STG - 1)) * STAGEB;
            const __half* ga = gA + pf * BK;
            const __half* gb = gB + pf * BK;
            CP16(base + stOff, ga);
            CP16(base + stOff + 16, ga + 8);
            CP16(base + TILEB + stOff, gb);
            CP16(base + TILEB + stOff + 16, gb + 8);
        }
        CP_COMMIT();

        const uint32_t soff = (it & (STG - 1)) * STAGEB;
#pragma unroll
        for (int kk = 0; kk < 2; ++kk) {
            uint32_t a[4][4];
            uint32_t b[4][2];
#pragma unroll
            for (int mt = 0; mt < 4; ++mt)
                ldsm_x4(a[mt][0], a[mt][1], a[mt][2], a[mt][3],
                        aBase + soff + (uint32_t)mt * (16 * ROWB) + kk * 32);
            ldsm_x4(b[0][0], b[0][1], b[1][0], b[1][1],
                    bBase + soff + kk * 32);
            ldsm_x4(b[2][0], b[2][1], b[3][0], b[3][1],
                    bBase + soff + (16 * ROWB) + kk * 32);
#pragma unroll
            for (int mt = 0; mt < 4; ++mt)
#pragma unroll
                for (int nt = 0; nt < 4; ++nt)
                    mma16816(acc[mt][nt], a[mt], b[nt]);
        }
    }

    const int r0 = by * BM + warpM * 64 + (lane >> 2);
    const int c0 = bx * BN + warpN * 32 + (lane & 3) * 2;
#pragma unroll
    for (int nt = 0; nt < 4; ++nt) {
        const int col = c0 + nt * 8;
        const float bx2 = bias[col], by2 = bias[col + 1];
#pragma unroll
        for (int mt = 0; mt < 4; ++mt) {
            const int row = r0 + mt * 16;
            float2 v0 = make_float2(acc[mt][nt][0] + bx2, acc[mt][nt][1] + by2);
            float2 v1 = make_float2(acc[mt][nt][2] + bx2, acc[mt][nt][3] + by2);
            *reinterpret_cast<float2*>(C + (size_t)row * DD + col) = v0;
            *reinterpret_cast<float2*>(C + (size_t)(row + 8) * DD + col) = v1;
        }
    }
}

// ============================================================
// Kernel 3: FUSED window-mean attention + writer CTAs.
// Worker CTAs: 48 x 512 threads = (chunk c 0..7) x (d-half 0..63).
// ============================================================
__global__ void __launch_bounds__(512)
attn_fused_aw(float* __restrict__ aw) {
    if (blockIdx.x < AWC) {
        if (aw != nullptr) aw_rows<512>(aw, CVT_ROWS, G1_ROW0, threadIdx.x);
        return;
    }
    __shared__ float tot[NCH][64 + 1];

    const int wb = blockIdx.x - AWC;
    const int half = wb & 1;
    const int bh = wb >> 1;
    const int b = bh / HH;
    const int h = bh % HH;
    const int c = threadIdx.x >> 6;          // 0..7
    const int dl = threadIdx.x & 63;
    const int d = half * 64 + dl;
    const int w = (1 << (h + 1)) - 1;
    const int q0 = c * QCH;

    const float* vp = g_V + ((size_t)b * SS + q0) * DD + h * HD + d;
    float* pp = g_P + ((size_t)(b * HH + h) * SS + q0) * HD + d;
    float acc = 0.0f;
#pragma unroll 8
    for (int i = 0; i < QCH; ++i) {
        acc += vp[(size_t)i * DD];
        pp[(size_t)i * HD] = acc;
    }
    tot[c][dl] = acc;
    __syncthreads();

    const int c2a = (q0 - w) >> 8;           // arithmetic shift; may be negative
    float run = 0.0f, offc = 0.0f, offA = 0.0f, offB = 0.0f;
#pragma unroll
    for (int cc = 0; cc < NCH; ++cc) {
        if (cc == c)       offc = run;
        if (cc == c2a)     offA = run;
        if (cc == c2a + 1) offB = run;
        run += tot[cc][dl];
    }

    const float* Pb = g_P + (size_t)(b * HH + h) * SS * HD + d;
    __half* op = g_As + ((size_t)b * SS + q0) * KK + (size_t)h * HD + d;
    const float invw = 1.0f / (float)w;
#pragma unroll 4
    for (int i = 0; i < QCH; ++i) {
        const int q = q0 + i;
        const float Pq = Pb[(size_t)q * HD] + offc;
        const int q2 = q - w;
        float prev, inv;
        if (q2 >= 0) {
            const int cc2 = q2 >> 8;
            const float off2 = (cc2 == c2a) ? offA : offB;
            prev = Pb[(size_t)q2 * HD] + off2;
            inv = invw;
        } else {
            prev = 0.0f;
            inv = 1.0f / (float)(q + 1);
        }
        op[(size_t)i * KK] = __float2half_rn((Pq - prev) * inv);
    }
}

// ============================================================
// Host launcher -- 4 launches, each carrying wall-rate writes
// ============================================================
extern "C" void kernel_launch(void* const* d_in, const int* in_sizes, int n_in,
                              void* d_out, int out_size) {
    const float* hs  = (const float*)d_in[0];
    const float* Wfc = (const float*)d_in[1];
    const float* bfc = (const float*)d_in[2];
    const float* Wpj = (const float*)d_in[3];
    const float* bpj = (const float*)d_in[4];
    float* out = (float*)d_out;

    void *pXs, *pAs, *pWs1, *pWs2, *pV;
    cudaGetSymbolAddress(&pXs,  g_Xs);
    cudaGetSymbolAddress(&pAs,  g_As);
    cudaGetSymbolAddress(&pWs1, g_Ws1);
    cudaGetSymbolAddress(&pWs2, g_Ws2);
    cudaGetSymbolAddress(&pV,   g_V);

    cudaFuncSetAttribute(gemm_fp16_aw,
                         cudaFuncAttributeMaxDynamicSharedMemorySize, GEMM_SMEM);

    long long need = (long long)OUT1_ELEMS + (long long)ATTN_ELEMS;
    float* aw = ((long long)out_size >= need) ? (out + OUT1_ELEMS) : nullptr;

    // 1) merged converts (+ aw rows [0, CVT_ROWS))
    cvt_all_aw<<<AWC + CVT_CTAS, 256>>>(
        (const float4*)hs, (const float4*)Wfc, (const float4*)Wpj,
        (uint2*)pXs, (uint2*)pWs1, (uint2*)pWs2, aw);

    // 2) V = X @ W_fc^T + b_fc   (+ aw rows [G1_ROW0, G1_ROW1))
    gemm_fp16_aw<<<AWC + NTILES, 256, GEMM_SMEM>>>(
        (const __half*)pXs, (const __half*)pWs1, (float*)pV, bfc,
        aw, G1_ROW0, G1_ROW1);

    // 3) fused window-mean attention (+ aw rows [CVT_ROWS, G1_ROW0))
    attn_fused_aw<<<AWC + BB * HH * 2, 512>>>(aw);

    // 4) out = attn_out @ W_proj^T + b_proj  (+ aw rows [G1_ROW1, NROWS))
    gemm_fp16_aw<<<AWC + NTILES, 256, GEMM_SMEM>>>(
        (const __half*)pAs, (const __half*)pWs2, out, bpj,
        aw, G1_ROW1, NROWS);
}

// round 13
// speedup vs baseline: 1.1737x; 1.0113x over previous
#include <cuda_runtime.h>
#include <cuda_fp16.h>
#include <cstdint>

// ============================================================
// Problem constants
// ============================================================
#define BB 2
#define SS 2048
#define DD 1536
#define HH 12
#define HD 128
#define KK 1536                 // GEMM K (plain fp16)
#define MM 4096                 // BB * SS
#define OUT1_ELEMS (MM * DD)    // 6291456
#define ATTN_ELEMS (BB * HH * SS * SS)  // 100663296
#define NROWS (BB * HH * SS)    // 49152 attn_weights rows
#define QCH 256                 // q-chunk for prefix scan
#define NCH (SS / QCH)          // 8 chunks

// GEMM tiling
#define BM 128
#define BN 128
#define BK 32
#define STG 4
#define ROWB 80                  // smem row stride in bytes -- conflict-free ldmatrix
#define TILEB (128 * ROWB)       // 10240 bytes per A or B tile
#define STAGEB (2 * TILEB)       // 20480 bytes per stage
#define GEMM_SMEM (STG * STAGEB) // 81920
#define NTILES ((DD / BN) * (MM / BM))   // 384 GEMM CTAs

// writer CTAs fused into every launch (low block indices)
#define AWC 148

// attn_weights row distribution across the 4 launches
// (cvt/attn windows absorb wall-rate writes that previously idled)
#define CVT_ROWS  2560
#define ATTN_ROWS 2560
#define G1_ROW0   (CVT_ROWS + ATTN_ROWS)            // 5120
#define G1_ROW1   (G1_ROW0 + (NROWS - G1_ROW0) / 2) // 27136
// gemm2 covers [G1_ROW1, NROWS)

// cvt sizes (in float4 units)
#define N4_X  (OUT1_ELEMS / 4)        // 1572864
#define N4_W  (DD * DD / 4)           // 589824
#define N4_ALL (N4_X + 2 * N4_W)      // 2752512
#define CVT_CTAS ((N4_ALL + 255) / 256)

// ============================================================
// Scratch (__device__ globals -- no allocation allowed)
// ============================================================
__device__ __half g_Xs[(size_t)MM * KK];   // fp16(hidden)
__device__ __half g_As[(size_t)MM * KK];   // fp16(attn out)
__device__ __half g_Ws1[(size_t)DD * KK];  // fp16(W_fc)
__device__ __half g_Ws2[(size_t)DD * KK];  // fp16(W_proj)
__device__ float  g_V[(size_t)MM * DD];    // fc output (value states)
__device__ float  g_P[(size_t)BB * HH * SS * HD];       // per-chunk local prefix

// ============================================================
// PTX helpers
// ============================================================
__device__ __forceinline__ uint32_t smem_to_u32(const void* p) {
    uint32_t a;
    asm("{ .reg .u64 t; cvta.to.shared.u64 t, %1; cvt.u32.u64 %0, t; }"
        : "=r"(a) : "l"(p));
    return a;
}

#define CP16(smem_u32, gptr) \
    asm volatile("cp.async.cg.shared.global [%0], [%1], 16;" \
        :: "r"(smem_u32), "l"(gptr))

#define CP_COMMIT() asm volatile("cp.async.commit_group;" ::: "memory")
#define CP_WAIT(n)  asm volatile("cp.async.wait_group %0;" :: "n"(n) : "memory")

__device__ __forceinline__ void ldsm_x4(uint32_t& r0, uint32_t& r1,
                                        uint32_t& r2, uint32_t& r3,
                                        uint32_t addr) {
    asm volatile("ldmatrix.sync.aligned.m8n8.x4.shared.b16 {%0,%1,%2,%3}, [%4];"
                 : "=r"(r0), "=r"(r1), "=r"(r2), "=r"(r3) : "r"(addr));
}

__device__ __forceinline__ void mma16816(float* c, const uint32_t* a,
                                         const uint32_t* b) {
    asm volatile(
        "mma.sync.aligned.m16n8k16.row.col.f32.f16.f16.f32 "
        "{%0,%1,%2,%3}, {%4,%5,%6,%7}, {%8,%9}, {%0,%1,%2,%3};"
        : "+f"(c[0]), "+f"(c[1]), "+f"(c[2]), "+f"(c[3])
        : "r"(a[0]), "r"(a[1]), "r"(a[2]), "r"(a[3]), "r"(b[0]), "r"(b[1]));
}

// ------------------------------------------------------------
// Generic attn_weights row writer: NT threads cover 2048 floats.
// ------------------------------------------------------------
template <int NT>
__device__ __forceinline__ void aw_rows(float* __restrict__ aw,
                                        int r0, int r1, int tid) {
    const int fpt = 2048 / NT;  // 8 for NT=256, 4 for NT=512
    const int k0 = tid * fpt;
    for (int row = r0 + blockIdx.x; row < r1; row += AWC) {
        const int q = row & (SS - 1);
        const int h = (row >> 11) % HH;
        const int w = (1 << (h + 1)) - 1;
        const int lo = q - w + 1;
        const int len = (q + 1 < w) ? (q + 1) : w;
        const float inv = 1.0f / (float)len;
        float* p = aw + (size_t)row * SS + k0;
#pragma unroll
        for (int j = 0; j < fpt; j += 4) {
            float4 v;
            int k;
            k = k0 + j + 0; v.x = (k <= q && k >= lo) ? inv : 0.0f;
            k = k0 + j + 1; v.y = (k <= q && k >= lo) ? inv : 0.0f;
            k = k0 + j + 2; v.z = (k <= q && k >= lo) ? inv : 0.0f;
            k = k0 + j + 3; v.w = (k <= q && k >= lo) ? inv : 0.0f;
            __stcs(reinterpret_cast<float4*>(p + j), v);
        }
    }
}

// ============================================================
// Kernel 1: merged fp32->fp16 convert (X, W_fc, W_proj) + writer CTAs
// ============================================================
__global__ void __launch_bounds__(256)
cvt_all_aw(const float4* __restrict__ hs, const float4* __restrict__ wfc,
           const float4* __restrict__ wpj, uint2* __restrict__ xs,
           uint2* __restrict__ w1, uint2* __restrict__ w2,
           float* __restrict__ aw) {
    if (blockIdx.x < AWC) {
        if (aw != nullptr) aw_rows<256>(aw, 0, CVT_ROWS, threadIdx.x);
        return;
    }
    int i = (blockIdx.x - AWC) * 256 + threadIdx.x;
    if (i >= N4_ALL) return;
    const float4* src;
    uint2* dst;
    int j;
    if (i < N4_X)            { src = hs;  dst = xs; j = i; }
    else if (i < N4_X + N4_W){ src = wfc; dst = w1; j = i - N4_X; }
    else                     { src = wpj; dst = w2; j = i - N4_X - N4_W; }
    float4 v = src[j];
    __half2 p0 = __halves2half2(__float2half_rn(v.x), __float2half_rn(v.y));
    __half2 p1 = __halves2half2(__float2half_rn(v.z), __float2half_rn(v.w));
    uint2 o;
    o.x = *reinterpret_cast<uint32_t*>(&p0);
    o.y = *reinterpret_cast<uint32_t*>(&p1);
    dst[j] = o;
}

// ============================================================
// Kernel 2: FUSED fp16 GEMM + attn_weights row writer.
// ============================================================
__global__ void __launch_bounds__(256, 2)
gemm_fp16_aw(const __half* __restrict__ A, const __half* __restrict__ Bw,
             float* __restrict__ C, const float* __restrict__ bias,
             float* __restrict__ aw, int awR0, int awR1) {
    if (blockIdx.x < AWC) {
        if (aw != nullptr) aw_rows<256>(aw, awR0, awR1, threadIdx.x);
        return;
    }

    const int bxy = blockIdx.x - AWC;
    const int bx = bxy % (DD / BN);   // N tile
    const int by = bxy / (DD / BN);   // M tile

    extern __shared__ char smem[];
    const uint32_t sb = smem_to_u32(smem);
    const int tid = threadIdx.x;
    const int lane = tid & 31;
    const int warp = tid >> 5;
    const int warpM = warp >> 2;
    const int warpN = warp & 3;

    const int ldRow = tid >> 1;
    const int ldCol = (tid & 1) * 2;
    const __half* gA = A + ((size_t)by * BM + ldRow) * KK + ldCol * 8;
    const __half* gB = Bw + ((size_t)bx * BN + ldRow) * KK + ldCol * 8;
    const uint32_t stOff = (uint32_t)ldRow * ROWB + (uint32_t)ldCol * 16;

    const int aRow = (lane & 7) + ((lane >> 3) & 1) * 8;
    const uint32_t aBase = sb + (uint32_t)(warpM * 64 + aRow) * ROWB
                              + (uint32_t)(lane >> 4) * 16;
    const int bRow = (lane & 7) + ((lane >> 4) & 1) * 8;
    const uint32_t bBase = sb + TILEB + (uint32_t)(warpN * 32 + bRow) * ROWB
                              + (uint32_t)((lane >> 3) & 1) * 16;

    float acc[4][4][4];
#pragma unroll
    for (int i = 0; i < 4; ++i)
#pragma unroll
        for (int j = 0; j < 4; ++j)
#pragma unroll
            for (int k = 0; k < 4; ++k) acc[i][j][k] = 0.0f;

    const int NIT = KK / BK;  // 48

#pragma unroll
    for (int s = 0; s < STG - 1; ++s) {
        const uint32_t base = sb + s * STAGEB;
        const __half* ga = gA + s * BK;
        const __half* gb = gB + s * BK;
        CP16(base + stOff, ga);
        CP16(base + stOff + 16, ga + 8);
        CP16(base + TILEB + stOff, gb);
        CP16(base + TILEB + stOff + 16, gb + 8);
        CP_COMMIT();
    }

    for (int it = 0; it < NIT; ++it) {
        CP_WAIT(STG - 2);
        __syncthreads();

        const int pf = it + STG - 1;
        if (pf < NIT) {
            const uint32_t base = sb + (pf & (STG - 1)) * STAGEB;
            const __half* ga = gA + pf * BK;
            const __half* gb = gB + pf * BK;
            CP16(base + stOff, ga);
            CP16(base + stOff + 16, ga + 8);
            CP16(base + TILEB + stOff, gb);
            CP16(base + TILEB + stOff + 16, gb + 8);
        }
        CP_COMMIT();

        const uint32_t soff = (it & (STG - 1)) * STAGEB;
#pragma unroll
        for (int kk = 0; kk < 2; ++kk) {
            uint32_t a[4][4];
            uint32_t b[4][2];
#pragma unroll
            for (int mt = 0; mt < 4; ++mt)
                ldsm_x4(a[mt][0], a[mt][1], a[mt][2], a[mt][3],
                        aBase + soff + (uint32_t)mt * (16 * ROWB) + kk * 32);
            ldsm_x4(b[0][0], b[0][1], b[1][0], b[1][1],
                    bBase + soff + kk * 32);
            ldsm_x4(b[2][0], b[2][1], b[3][0], b[3][1],
                    bBase + soff + (16 * ROWB) + kk * 32);
#pragma unroll
            for (int mt = 0; mt < 4; ++mt)
#pragma unroll
                for (int nt = 0; nt < 4; ++nt)
                    mma16816(acc[mt][nt], a[mt], b[nt]);
        }
    }

    const int r0 = by * BM + warpM * 64 + (lane >> 2);
    const int c0 = bx * BN + warpN * 32 + (lane & 3) * 2;
#pragma unroll
    for (int nt = 0; nt < 4; ++nt) {
        const int col = c0 + nt * 8;
        const float bx2 = bias[col], by2 = bias[col + 1];
#pragma unroll
        for (int mt = 0; mt < 4; ++mt) {
            const int row = r0 + mt * 16;
            float2 v0 = make_float2(acc[mt][nt][0] + bx2, acc[mt][nt][1] + by2);
            float2 v1 = make_float2(acc[mt][nt][2] + bx2, acc[mt][nt][3] + by2);
            *reinterpret_cast<float2*>(C + (size_t)row * DD + col) = v0;
            *reinterpret_cast<float2*>(C + (size_t)(row + 8) * DD + col) = v1;
        }
    }
}

// ============================================================
// Kernel 3: FUSED window-mean attention + writer CTAs.
// Worker CTAs: 48 x 512 threads = (chunk c 0..7) x (d-half 0..63).
// ============================================================
__global__ void __launch_bounds__(512)
attn_fused_aw(float* __restrict__ aw) {
    if (blockIdx.x < AWC) {
        if (aw != nullptr) aw_rows<512>(aw, CVT_ROWS, G1_ROW0, threadIdx.x);
        return;
    }
    __shared__ float tot[NCH][64 + 1];

    const int wb = blockIdx.x - AWC;
    const int half = wb & 1;
    const int bh = wb >> 1;
    const int b = bh / HH;
    const int h = bh % HH;
    const int c = threadIdx.x >> 6;          // 0..7
    const int dl = threadIdx.x & 63;
    const int d = half * 64 + dl;
    const int w = (1 << (h + 1)) - 1;
    const int q0 = c * QCH;

    const float* vp = g_V + ((size_t)b * SS + q0) * DD + h * HD + d;
    float* pp = g_P + ((size_t)(b * HH + h) * SS + q0) * HD + d;
    float acc = 0.0f;
#pragma unroll 8
    for (int i = 0; i < QCH; ++i) {
        acc += vp[(size_t)i * DD];
        pp[(size_t)i * HD] = acc;
    }
    tot[c][dl] = acc;
    __syncthreads();

    const int c2a = (q0 - w) >> 8;           // arithmetic shift; may be negative
    float run = 0.0f, offc = 0.0f, offA = 0.0f, offB = 0.0f;
#pragma unroll
    for (int cc = 0; cc < NCH; ++cc) {
        if (cc == c)       offc = run;
        if (cc == c2a)     offA = run;
        if (cc == c2a + 1) offB = run;
        run += tot[cc][dl];
    }

    const float* Pb = g_P + (size_t)(b * HH + h) * SS * HD + d;
    __half* op = g_As + ((size_t)b * SS + q0) * KK + (size_t)h * HD + d;
    const float invw = 1.0f / (float)w;
#pragma unroll 4
    for (int i = 0; i < QCH; ++i) {
        const int q = q0 + i;
        const float Pq = Pb[(size_t)q * HD] + offc;
        const int q2 = q - w;
        float prev, inv;
        if (q2 >= 0) {
            const int cc2 = q2 >> 8;
            const float off2 = (cc2 == c2a) ? offA : offB;
            prev = Pb[(size_t)q2 * HD] + off2;
            inv = invw;
        } else {
            prev = 0.0f;
            inv = 1.0f / (float)(q + 1);
        }
        op[(size_t)i * KK] = __float2half_rn((Pq - prev) * inv);
    }
}

// ============================================================
// Host launcher -- 4 launches, each carrying wall-rate writes
// ============================================================
extern "C" void kernel_launch(void* const* d_in, const int* in_sizes, int n_in,
                              void* d_out, int out_size) {
    const float* hs  = (const float*)d_in[0];
    const float* Wfc = (const float*)d_in[1];
    const float* bfc = (const float*)d_in[2];
    const float* Wpj = (const float*)d_in[3];
    const float* bpj = (const float*)d_in[4];
    float* out = (float*)d_out;

    void *pXs, *pAs, *pWs1, *pWs2, *pV;
    cudaGetSymbolAddress(&pXs,  g_Xs);
    cudaGetSymbolAddress(&pAs,  g_As);
    cudaGetSymbolAddress(&pWs1, g_Ws1);
    cudaGetSymbolAddress(&pWs2, g_Ws2);
    cudaGetSymbolAddress(&pV,   g_V);

    cudaFuncSetAttribute(gemm_fp16_aw,
                         cudaFuncAttributeMaxDynamicSharedMemorySize, GEMM_SMEM);

    long long need = (long long)OUT1_ELEMS + (long long)ATTN_ELEMS;
    float* aw = ((long long)out_size >= need) ? (out + OUT1_ELEMS) : nullptr;

    // 1) merged converts (+ aw rows [0, CVT_ROWS))
    cvt_all_aw<<<AWC + CVT_CTAS, 256>>>(
        (const float4*)hs, (const float4*)Wfc, (const float4*)Wpj,
        (uint2*)pXs, (uint2*)pWs1, (uint2*)pWs2, aw);

    // 2) V = X @ W_fc^T + b_fc   (+ aw rows [G1_ROW0, G1_ROW1))
    gemm_fp16_aw<<<AWC + NTILES, 256, GEMM_SMEM>>>(
        (const __half*)pXs, (const __half*)pWs1, (float*)pV, bfc,
        aw, G1_ROW0, G1_ROW1);

    // 3) fused window-mean attention (+ aw rows [CVT_ROWS, G1_ROW0))
    attn_fused_aw<<<AWC + BB * HH * 2, 512>>>(aw);

    // 4) out = attn_out @ W_proj^T + b_proj  (+ aw rows [G1_ROW1, NROWS))
    gemm_fp16_aw<<<AWC + NTILES, 256, GEMM_SMEM>>>(
        (const __half*)pAs, (const __half*)pWs2, out, bpj,
        aw, G1_ROW1, NROWS);
}